// round 6
// baseline (speedup 1.0000x reference)
#include <cuda_runtime.h>

#define S      256
#define NB     128
#define L      256
#define NL     64
#define VOCAB  32000

typedef unsigned long long ull;

// K1 dynamic smem:
//   TsmU2 [16][256] ulonglong2 = 65536 B  (T tail: 2 states x 32 j per thread)
//   xs    [2][2][256] float    =  4096 B  (double-buffered state vec per chain)
//   tok   [2][256] int         =  2048 B
#define SMEM1  (65536 + 4096 + 2048)

// scratch
__device__ float g_fwd[L * NB * S];   // fprime[t][b][s]  (pre-e-multiply forward)
__device__ float g_bwd[L * NB * S];   // b[t][b][s]

__device__ __forceinline__ void ffma2(ull &a, ull b, ull c) {
    asm("fma.rn.f32x2 %0, %1, %2, %0;" : "+l"(a) : "l"(b), "l"(c));
}
__device__ __forceinline__ float hsum1(ull a) {
    float2 v = *reinterpret_cast<float2*>(&a);
    return v.x + v.y;
}

// ---------------------------------------------------------------------------
// K1: 128 CTAs x 256 threads, 2 chains per CTA. bid<64: forward for batches
// (2p, 2p+1); bid>=64: backward. Thread (warp w, lane l): hf=l>>4 selects the
// j-half [hf*128, hf*128+128); it owns states q=w*16+(l&15) and q+128.
// Half-dot-products combine via shfl_xor(16) within the warp -> ONE barrier
// per step. Per state: 96 T values in regs, 32 in smem. Packed fma.rn.f32x2.
// ---------------------------------------------------------------------------
__global__ __launch_bounds__(256, 1)
void hmm_scan_kernel(const void* __restrict__ sent_raw,
                     const float* __restrict__ emb,
                     const float* __restrict__ Tm)
{
    extern __shared__ char smem_raw[];
    ulonglong2* TsmU2 = (ulonglong2*)smem_raw;              // [16][256]
    float* xs  = (float*)(smem_raw + 65536);                // [p][c][256]
    int*   tok = (int*)  (smem_raw + 65536 + 4096);         // [c][256]
    __shared__ int s_i64;

    const int  tid = threadIdx.x;
    const int  w   = tid >> 5;
    const int  l   = tid & 31;
    const int  hf  = l >> 4;             // j-half
    const int  q   = w * 16 + (l & 15);  // base state (thread also owns q+128)
    const int  j0  = hf << 7;            // j-range start
    const int  bid = blockIdx.x;
    const bool bwd = (bid >= 64);
    const int  b0  = (bid & 63) * 2;
    const int  b1  = b0 + 1;

    // --- detect sentences dtype (int64 vs int32) ---
    if (tid == 0) {
        const long long* s64 = (const long long*)sent_raw;
        int f = 1;
        for (int k = 0; k < 64; k++) {
            long long v = s64[k];
            if (v < 0 || v >= VOCAB) { f = 0; break; }
        }
        s_i64 = f;
    }
    __syncthreads();

    // --- tokens for both chains ---
    if (s_i64) {
        const long long* s64 = (const long long*)sent_raw;
        tok[tid]       = (int)s64[b0 * L + tid];
        tok[256 + tid] = (int)s64[b1 * L + tid];
    } else {
        const int* s32 = (const int*)sent_raw;
        tok[tid]       = s32[b0 * L + tid];
        tok[256 + tid] = s32[b1 * L + tid];
    }

    // --- T slices: 2 states x 128 j -> 96 in regs (48 ull), 32 in smem (8 u2) per state
    ull TrU[2][48];
    #pragma unroll
    for (int k = 0; k < 2; k++) {
        const int sk = q + (k << 7);
        if (!bwd) {
            const float4* row = (const float4*)(Tm + sk * S + j0);
            #pragma unroll
            for (int g = 0; g < 24; g++) ((float4*)TrU[k])[g] = row[g];
            #pragma unroll
            for (int g = 0; g < 8; g++)
                TsmU2[(k * 8 + g) * 256 + tid] = ((const ulonglong2*)row)[24 + g];
        } else {
            #pragma unroll
            for (int g = 0; g < 24; g++) {
                int j = j0 + 4 * g;
                ((float4*)TrU[k])[g] = make_float4(
                    Tm[(j + 0) * S + sk], Tm[(j + 1) * S + sk],
                    Tm[(j + 2) * S + sk], Tm[(j + 3) * S + sk]);
            }
            #pragma unroll
            for (int g = 0; g < 8; g++) {
                int j = j0 + 96 + 4 * g;
                float4 f4 = make_float4(
                    Tm[(j + 0) * S + sk], Tm[(j + 1) * S + sk],
                    Tm[(j + 2) * S + sk], Tm[(j + 3) * S + sk]);
                TsmU2[(k * 8 + g) * 256 + tid] = *reinterpret_cast<ulonglong2*>(&f4);
            }
        }
    }

    float* outg = bwd ? g_bwd : g_fwd;

    // --- step 0: x = e(t0); store f'(=1) / b(=e) ---
    const int t0 = bwd ? (L - 1) : 0;
    {
        float e0 = emb[tok[t0] * S + tid];
        float e1 = emb[tok[256 + t0] * S + tid];
        if (!bwd) {
            outg[(t0 * NB + b0) * S + tid] = 1.0f;
            outg[(t0 * NB + b1) * S + tid] = 1.0f;
        } else {
            outg[(t0 * NB + b0) * S + tid] = e0;
            outg[(t0 * NB + b1) * S + tid] = e1;
        }
        xs[tid]       = e0;
        xs[256 + tid] = e1;
    }
    __syncthreads();

    const int dt = bwd ? -1 : 1;
    int t = t0;
    int p = 0;

    for (int step = 1; step < L; step++) {
        t += dt;
        // e prefetch for states q, q+128, both chains (consumed after matvec)
        const int tk0 = tok[t] * S;
        const int tk1 = tok[256 + t] * S;
        float e00 = emb[tk0 + q];
        float e10 = emb[tk0 + q + 128];
        float e01 = emb[tk1 + q];
        float e11 = emb[tk1 + q + 128];

        const ulonglong2* X0 = (const ulonglong2*)(xs + p * 512 + j0);
        const ulonglong2* X1 = (const ulonglong2*)(xs + p * 512 + 256 + j0);

        ull a00 = 0, a10 = 0, a01 = 0, a11 = 0;   // [state k][chain c]

        #pragma unroll
        for (int g = 0; g < 24; g++) {
            ulonglong2 x0 = X0[g];
            ulonglong2 x1 = X1[g];
            ffma2(a00, TrU[0][2 * g],     x0.x);
            ffma2(a00, TrU[0][2 * g + 1], x0.y);
            ffma2(a01, TrU[0][2 * g],     x1.x);
            ffma2(a01, TrU[0][2 * g + 1], x1.y);
            ffma2(a10, TrU[1][2 * g],     x0.x);
            ffma2(a10, TrU[1][2 * g + 1], x0.y);
            ffma2(a11, TrU[1][2 * g],     x1.x);
            ffma2(a11, TrU[1][2 * g + 1], x1.y);
        }
        #pragma unroll
        for (int g = 0; g < 8; g++) {
            ulonglong2 x0 = X0[24 + g];
            ulonglong2 x1 = X1[24 + g];
            ulonglong2 t0v = TsmU2[g * 256 + tid];
            ulonglong2 t1v = TsmU2[(8 + g) * 256 + tid];
            ffma2(a00, t0v.x, x0.x);
            ffma2(a00, t0v.y, x0.y);
            ffma2(a01, t0v.x, x1.x);
            ffma2(a01, t0v.y, x1.y);
            ffma2(a10, t1v.x, x0.x);
            ffma2(a10, t1v.y, x0.y);
            ffma2(a11, t1v.x, x1.x);
            ffma2(a11, t1v.y, x1.y);
        }

        // combine halves within the warp (lane pair l <-> l^16)
        float s00 = hsum1(a00); s00 += __shfl_xor_sync(0xffffffffu, s00, 16);
        float s10 = hsum1(a10); s10 += __shfl_xor_sync(0xffffffffu, s10, 16);
        float s01 = hsum1(a01); s01 += __shfl_xor_sync(0xffffffffu, s01, 16);
        float s11 = hsum1(a11); s11 += __shfl_xor_sync(0xffffffffu, s11, 16);

        float nx00 = s00 * e00;
        float nx10 = s10 * e10;
        float nx01 = s01 * e01;
        float nx11 = s11 * e11;

        if (hf == 0) {
            // new state vector
            float* xn = xs + (p ^ 1) * 512;
            xn[q]             = nx00;
            xn[q + 128]       = nx10;
            xn[256 + q]       = nx01;
            xn[256 + q + 128] = nx11;
            // output (fire-and-forget before the barrier)
            if (!bwd) {
                outg[(t * NB + b0) * S + q]       = s00;
                outg[(t * NB + b0) * S + q + 128] = s10;
                outg[(t * NB + b1) * S + q]       = s01;
                outg[(t * NB + b1) * S + q + 128] = s11;
            } else {
                outg[(t * NB + b0) * S + q]       = nx00;
                outg[(t * NB + b0) * S + q + 128] = nx10;
                outg[(t * NB + b1) * S + q]       = nx01;
                outg[(t * NB + b1) * S + q + 128] = nx11;
            }
        }

        p ^= 1;
        __syncthreads();
    }
}

// ---------------------------------------------------------------------------
// K2: score[b][t][n] = sum_s fprime[t][b][s] * b[t][b][s] * O[s][n]
// (unchanged — ~39.6 us)
// ---------------------------------------------------------------------------
__global__ __launch_bounds__(256, 4)
void hmm_proj_kernel(const float* __restrict__ Om, float* __restrict__ outp)
{
    __shared__ float esm[64 * 68];
    __shared__ float osm[64 * 64];

    const int tid = threadIdx.x;
    const int r0  = blockIdx.x * 64;
    const int rg  = tid >> 4;
    const int cg  = tid & 15;

    float4 acc0 = make_float4(0.f, 0.f, 0.f, 0.f);
    float4 acc1 = make_float4(0.f, 0.f, 0.f, 0.f);
    float4 acc2 = make_float4(0.f, 0.f, 0.f, 0.f);
    float4 acc3 = make_float4(0.f, 0.f, 0.f, 0.f);

    for (int s0 = 0; s0 < S; s0 += 64) {
        if (s0) __syncthreads();
        #pragma unroll
        for (int k = 0; k < 4; k++) {
            int id4 = k * 256 + tid;
            int rr  = id4 >> 4;
            int ss  = (id4 & 15) * 4;
            int r   = r0 + rr;
            float4 fv = *(const float4*)&g_fwd[r * S + s0 + ss];
            float4 bv = *(const float4*)&g_bwd[r * S + s0 + ss];
            float4 ev = make_float4(fv.x * bv.x, fv.y * bv.y, fv.z * bv.z, fv.w * bv.w);
            *(float4*)&esm[rr * 68 + ss] = ev;
        }
        #pragma unroll
        for (int k = 0; k < 4; k++) {
            int id4 = k * 256 + tid;
            int ss  = id4 >> 4;
            int n   = (id4 & 15) * 4;
            *(float4*)&osm[ss * 64 + n] = *(const float4*)&Om[(s0 + ss) * NL + n];
        }
        __syncthreads();

        #pragma unroll 8
        for (int sc = 0; sc < 64; sc++) {
            float4 ov = *(const float4*)&osm[sc * 64 + cg * 4];
            float e0 = esm[(rg * 4 + 0) * 68 + sc];
            float e1 = esm[(rg * 4 + 1) * 68 + sc];
            float e2 = esm[(rg * 4 + 2) * 68 + sc];
            float e3 = esm[(rg * 4 + 3) * 68 + sc];
            acc0.x += e0 * ov.x; acc0.y += e0 * ov.y; acc0.z += e0 * ov.z; acc0.w += e0 * ov.w;
            acc1.x += e1 * ov.x; acc1.y += e1 * ov.y; acc1.z += e1 * ov.z; acc1.w += e1 * ov.w;
            acc2.x += e2 * ov.x; acc2.y += e2 * ov.y; acc2.z += e2 * ov.z; acc2.w += e2 * ov.w;
            acc3.x += e3 * ov.x; acc3.y += e3 * ov.y; acc3.z += e3 * ov.z; acc3.w += e3 * ov.w;
        }
    }

    #pragma unroll
    for (int k = 0; k < 4; k++) {
        int r  = r0 + rg * 4 + k;
        int t  = r >> 7;
        int bb = r & 127;
        float4 v = (k == 0) ? acc0 : (k == 1) ? acc1 : (k == 2) ? acc2 : acc3;
        *(float4*)&outp[(bb * L + t) * NL + cg * 4] = v;
    }
}

extern "C" void kernel_launch(void* const* d_in, const int* in_sizes, int n_in,
                              void* d_out, int out_size)
{
    (void)in_sizes; (void)n_in; (void)out_size;
    const void*  sent = d_in[0];
    const float* emb  = (const float*)d_in[1];
    const float* Tm   = (const float*)d_in[2];
    const float* Om   = (const float*)d_in[3];
    float* outp = (float*)d_out;

    cudaFuncSetAttribute(hmm_scan_kernel,
                         cudaFuncAttributeMaxDynamicSharedMemorySize, SMEM1);

    hmm_scan_kernel<<<128, 256, SMEM1>>>(sent, emb, Tm);
    hmm_proj_kernel<<<512, 256>>>(Om, outp);
}

// round 7
// speedup vs baseline: 1.2010x; 1.2010x over previous
#include <cuda_runtime.h>

#define S      256
#define NB     128
#define L      256
#define NL     64
#define VOCAB  32000

typedef unsigned long long ull;

// K1 dynamic smem:
//   TsmU2 [16][256] ulonglong2 = 65536 B   (T tail: 2 states x 32 j per thread)
//   xs    [2][2][256] float    =  4096 B   (double-buffered state vec per chain)
//   part  [2][2][256] float    =  4096 B   (partials: [chain][half][state])
//   tok   [2][256] int         =  2048 B
#define SMEM1  (65536 + 4096 + 4096 + 2048)

// scratch
__device__ float g_fwd[L * NB * S];   // fprime[t][b][s]  (pre-e-multiply forward)
__device__ float g_bwd[L * NB * S];   // b[t][b][s]

__device__ __forceinline__ void ffma2(ull &a, ull b, ull c) {
    asm("fma.rn.f32x2 %0, %1, %2, %0;" : "+l"(a) : "l"(b), "l"(c));
}
__device__ __forceinline__ float hsum2(ull lo, ull hi) {
    float2 a = *reinterpret_cast<float2*>(&lo);
    float2 b = *reinterpret_cast<float2*>(&hi);
    return (a.x + a.y) + (b.x + b.y);
}
__device__ __forceinline__ ull packdup(float e) {
    ull r;
    asm("mov.b64 %0, {%1, %1};" : "=l"(r) : "f"(e));
    return r;
}

// ---------------------------------------------------------------------------
// K1 (R3 topology, restored): 128 CTAs x 256 threads, 2 chains per CTA.
// bid<64: forward for batches (2p,2p+1); bid>=64: backward.
// Thread (h=tid>>7, u=tid&127) owns states {u, u+128} restricted to
// j in [128h, 128h+128). Packed fma.rn.f32x2 over j-pairs; halves combined
// via smem partials (2 barriers/step). Output STG deferred out of the
// critical inter-barrier window.
// ---------------------------------------------------------------------------
__global__ __launch_bounds__(256, 1)
void hmm_scan_kernel(const void* __restrict__ sent_raw,
                     const float* __restrict__ emb,
                     const float* __restrict__ Tm)
{
    extern __shared__ char smem_raw[];
    ulonglong2* TsmU2 = (ulonglong2*)smem_raw;              // [16][256]
    float* xs   = (float*)(smem_raw + 65536);               // [p][c][256]
    float* part = (float*)(smem_raw + 65536 + 4096);        // [c][h][256]
    int*   tok  = (int*)  (smem_raw + 65536 + 8192);        // [c][256]
    __shared__ int s_i64;

    const int  tid = threadIdx.x;
    const int  h   = tid >> 7;
    const int  u   = tid & 127;
    const int  j0  = h << 7;
    const int  bid = blockIdx.x;
    const bool bwd = (bid >= 64);
    const int  b0  = (bid & 63) * 2;
    const int  b1  = b0 + 1;

    // --- detect sentences dtype (int64 vs int32) ---
    if (tid == 0) {
        const long long* s64 = (const long long*)sent_raw;
        int f = 1;
        for (int k = 0; k < 64; k++) {
            long long v = s64[k];
            if (v < 0 || v >= VOCAB) { f = 0; break; }
        }
        s_i64 = f;
    }
    __syncthreads();

    // --- tokens for both chains ---
    if (s_i64) {
        const long long* s64 = (const long long*)sent_raw;
        tok[tid]       = (int)s64[b0 * L + tid];
        tok[256 + tid] = (int)s64[b1 * L + tid];
    } else {
        const int* s32 = (const int*)sent_raw;
        tok[tid]       = s32[b0 * L + tid];
        tok[256 + tid] = s32[b1 * L + tid];
    }

    // --- T slices: states u (A) and u+128 (B), j in [j0, j0+128):
    //     96 floats in regs (48 ull), 32 floats in smem (8 ulonglong2) each ---
    ull TrA[48], TrB[48];
    if (!bwd) {
        const float4* rowA = (const float4*)(Tm + u * S + j0);
        const float4* rowB = (const float4*)(Tm + (u + 128) * S + j0);
        #pragma unroll
        for (int g = 0; g < 24; g++) {
            ((float4*)TrA)[g] = rowA[g];
            ((float4*)TrB)[g] = rowB[g];
        }
        #pragma unroll
        for (int g = 0; g < 8; g++) {
            TsmU2[g * 256 + tid]       = ((const ulonglong2*)rowA)[24 + g];
            TsmU2[(8 + g) * 256 + tid] = ((const ulonglong2*)rowB)[24 + g];
        }
    } else {
        #pragma unroll
        for (int g = 0; g < 24; g++) {
            int j = j0 + 4 * g;
            ((float4*)TrA)[g] = make_float4(Tm[(j+0)*S + u],       Tm[(j+1)*S + u],
                                            Tm[(j+2)*S + u],       Tm[(j+3)*S + u]);
            ((float4*)TrB)[g] = make_float4(Tm[(j+0)*S + u + 128], Tm[(j+1)*S + u + 128],
                                            Tm[(j+2)*S + u + 128], Tm[(j+3)*S + u + 128]);
        }
        #pragma unroll
        for (int g = 0; g < 8; g++) {
            int j = j0 + 96 + 4 * g;
            float4 a4 = make_float4(Tm[(j+0)*S + u],       Tm[(j+1)*S + u],
                                    Tm[(j+2)*S + u],       Tm[(j+3)*S + u]);
            float4 b4 = make_float4(Tm[(j+0)*S + u + 128], Tm[(j+1)*S + u + 128],
                                    Tm[(j+2)*S + u + 128], Tm[(j+3)*S + u + 128]);
            TsmU2[g * 256 + tid]       = *reinterpret_cast<ulonglong2*>(&a4);
            TsmU2[(8 + g) * 256 + tid] = *reinterpret_cast<ulonglong2*>(&b4);
        }
    }

    float* outg = bwd ? g_bwd : g_fwd;

    // --- step 0 ---
    const int t0 = bwd ? (L - 1) : 0;
    {
        float e0 = emb[tok[t0] * S + tid];
        float e1 = emb[tok[256 + t0] * S + tid];
        if (!bwd) {
            outg[(t0 * NB + b0) * S + tid] = 1.0f;    // fprime[0] = 1
            outg[(t0 * NB + b1) * S + tid] = 1.0f;
        } else {
            outg[(t0 * NB + b0) * S + tid] = e0;      // b[L-1] = e[L-1]
            outg[(t0 * NB + b1) * S + tid] = e1;
        }
        xs[tid]       = e0;
        xs[256 + tid] = e1;
    }
    __syncthreads();

    const int dt = bwd ? -1 : 1;
    int t = t0;
    int p = 0;

    // deferred-output registers
    float o0 = 0.f, o1 = 0.f;
    int   tprev = -1;

    for (int step = 1; step < L; step++) {
        t += dt;

        // deferred output write from previous step (overlaps this matvec)
        if (tprev >= 0) {
            outg[(tprev * NB + b0) * S + tid] = o0;
            outg[(tprev * NB + b1) * S + tid] = o1;
        }

        // e prefetch: consumed only after bar1
        float en0 = emb[tok[t] * S + tid];
        float en1 = emb[tok[256 + t] * S + tid];

        const ulonglong2* X0 = (const ulonglong2*)(xs + p * 512 + j0);
        const ulonglong2* X1 = (const ulonglong2*)(xs + p * 512 + 256 + j0);

        ull a00l = 0, a00h = 0, a01l = 0, a01h = 0;   // state u:     chain0, chain1
        ull a10l = 0, a10h = 0, a11l = 0, a11h = 0;   // state u+128

        #pragma unroll
        for (int g = 0; g < 24; g++) {
            ulonglong2 x0 = X0[g];
            ulonglong2 x1 = X1[g];
            ffma2(a00l, TrA[2*g],   x0.x); ffma2(a00h, TrA[2*g+1], x0.y);
            ffma2(a01l, TrA[2*g],   x1.x); ffma2(a01h, TrA[2*g+1], x1.y);
            ffma2(a10l, TrB[2*g],   x0.x); ffma2(a10h, TrB[2*g+1], x0.y);
            ffma2(a11l, TrB[2*g],   x1.x); ffma2(a11h, TrB[2*g+1], x1.y);
        }
        #pragma unroll
        for (int g = 0; g < 8; g++) {
            ulonglong2 tA = TsmU2[g * 256 + tid];
            ulonglong2 tB = TsmU2[(8 + g) * 256 + tid];
            ulonglong2 x0 = X0[24 + g];
            ulonglong2 x1 = X1[24 + g];
            ffma2(a00l, tA.x, x0.x); ffma2(a00h, tA.y, x0.y);
            ffma2(a01l, tA.x, x1.x); ffma2(a01h, tA.y, x1.y);
            ffma2(a10l, tB.x, x0.x); ffma2(a10h, tB.y, x0.y);
            ffma2(a11l, tB.x, x1.x); ffma2(a11h, tB.y, x1.y);
        }

        // partials: part[c][h][s]
        part[h * 256 + u]             = hsum2(a00l, a00h);
        part[h * 256 + u + 128]       = hsum2(a10l, a10h);
        part[512 + h * 256 + u]       = hsum2(a01l, a01h);
        part[512 + h * 256 + u + 128] = hsum2(a11l, a11h);
        __syncthreads();

        // combine: thread tid handles state tid, both chains
        float s0 = part[tid]       + part[256 + tid];
        float s1 = part[512 + tid] + part[768 + tid];
        float nx0 = s0 * en0;
        float nx1 = s1 * en1;

        // stash outputs for deferred write (after bar2)
        o0 = bwd ? nx0 : s0;
        o1 = bwd ? nx1 : s1;
        tprev = t;

        p ^= 1;
        xs[p * 512 + tid]       = nx0;
        xs[p * 512 + 256 + tid] = nx1;
        __syncthreads();
    }

    // final deferred write
    outg[(tprev * NB + b0) * S + tid] = o0;
    outg[(tprev * NB + b1) * S + tid] = o1;
}

// ---------------------------------------------------------------------------
// K2: score[b][t][n] = sum_s fprime[t][b][s] * b[t][b][s] * O[s][n]
// Tiled SIMT GEMM, now with packed fma.rn.f32x2 over n-pairs.
// ---------------------------------------------------------------------------
__global__ __launch_bounds__(256, 4)
void hmm_proj_kernel(const float* __restrict__ Om, float* __restrict__ outp)
{
    __shared__ float esm[64 * 68];
    __shared__ float osm[64 * 64];

    const int tid = threadIdx.x;
    const int r0  = blockIdx.x * 64;
    const int rg  = tid >> 4;
    const int cg  = tid & 15;

    // 4 rows x 4 cols per thread; accumulators as f32x2 pairs
    ull acc01[4] = {0,0,0,0};   // cols (n0,n1) for rows 0..3
    ull acc23[4] = {0,0,0,0};   // cols (n2,n3)

    for (int s0 = 0; s0 < S; s0 += 64) {
        if (s0) __syncthreads();
        #pragma unroll
        for (int k = 0; k < 4; k++) {
            int id4 = k * 256 + tid;
            int rr  = id4 >> 4;
            int ss  = (id4 & 15) * 4;
            int r   = r0 + rr;
            float4 fv = *(const float4*)&g_fwd[r * S + s0 + ss];
            float4 bv = *(const float4*)&g_bwd[r * S + s0 + ss];
            float4 ev = make_float4(fv.x * bv.x, fv.y * bv.y, fv.z * bv.z, fv.w * bv.w);
            *(float4*)&esm[rr * 68 + ss] = ev;
        }
        #pragma unroll
        for (int k = 0; k < 4; k++) {
            int id4 = k * 256 + tid;
            int ss  = id4 >> 4;
            int n   = (id4 & 15) * 4;
            *(float4*)&osm[ss * 64 + n] = *(const float4*)&Om[(s0 + ss) * NL + n];
        }
        __syncthreads();

        #pragma unroll 8
        for (int sc = 0; sc < 64; sc++) {
            ulonglong2 ov = *(const ulonglong2*)&osm[sc * 64 + cg * 4];
            #pragma unroll
            for (int k = 0; k < 4; k++) {
                ull ep = packdup(esm[(rg * 4 + k) * 68 + sc]);
                ffma2(acc01[k], ep, ov.x);
                ffma2(acc23[k], ep, ov.y);
            }
        }
    }

    // write: r = t*128 + b  ->  out[(b*L + t)*NL + n]
    #pragma unroll
    for (int k = 0; k < 4; k++) {
        int r  = r0 + rg * 4 + k;
        int t  = r >> 7;
        int bb = r & 127;
        float2 lo = *reinterpret_cast<float2*>(&acc01[k]);
        float2 hi = *reinterpret_cast<float2*>(&acc23[k]);
        float4 v  = make_float4(lo.x, lo.y, hi.x, hi.y);
        *(float4*)&outp[(bb * L + t) * NL + cg * 4] = v;
    }
}

extern "C" void kernel_launch(void* const* d_in, const int* in_sizes, int n_in,
                              void* d_out, int out_size)
{
    (void)in_sizes; (void)n_in; (void)out_size;
    const void*  sent = d_in[0];
    const float* emb  = (const float*)d_in[1];
    const float* Tm   = (const float*)d_in[2];
    const float* Om   = (const float*)d_in[3];
    float* outp = (float*)d_out;

    cudaFuncSetAttribute(hmm_scan_kernel,
                         cudaFuncAttributeMaxDynamicSharedMemorySize, SMEM1);

    hmm_scan_kernel<<<128, 256, SMEM1>>>(sent, emb, Tm);
    hmm_proj_kernel<<<512, 256>>>(Om, outp);
}